// round 1
// baseline (speedup 1.0000x reference)
#include <cuda_runtime.h>
#include <cstdint>
#include <cstddef>

// MultiDimHiPPO2: out[b, 0:512,   m] = base[b, 0:512,   m] + sum_k cos(2pi*(k+tok)*n/8192) * slice[b,k,m]
//                 out[b, 512:1024,m] = base[b, 512:1024,m] + sum_k sin(2pi*(k+tok)*n/8192) * slice[b,k,m]
// B=4, K=4096, M=1024, NFREQ=512.
//
// Strategy: tf32 mma.sync GEMM, trig matrix generated on the fly via exact
// integer phase reduction p = (k+tok)*n mod 8192  ->  angle in [-pi, pi)
// -> __sincosf (one call fills both the cos row and the sin row of the tile).

#define KDIM   4096
#define MDIM   1024
#define BK     32
#define BM     128      // 64 cos rows + 64 sin rows (same frequencies)
#define BN     128
#define AS_STRIDE 40    // 128 rows x 40 (pad) -> 2-way max conflict on frag loads
#define BS_STRIDE 136   // 32 rows  x 136 (pad 8) -> conflict-free frag loads

__device__ __forceinline__ uint32_t f2tf32(float x) {
    uint32_t r;
    asm("cvt.rna.tf32.f32 %0, %1;" : "=r"(r) : "f"(x));
    return r;
}

__global__ void __launch_bounds__(256) hippo_tf32_kernel(
    const float* __restrict__ base,
    const float* __restrict__ slice,
    const int*   __restrict__ tokp,
    float*       __restrict__ out)
{
    __shared__ uint32_t As[BM * AS_STRIDE];   // [row(local 0..127)][k(0..31)]
    __shared__ uint32_t Bs[BK * BS_STRIDE];   // [k(0..31)][m(0..127)]

    const int tid  = threadIdx.x;
    const int warp = tid >> 5;
    const int lane = tid & 31;
    const int g    = lane >> 2;      // group id 0..7
    const int tig  = lane & 3;       // thread-in-group 0..3

    const int m0 = blockIdx.x * BN;
    const int nb = blockIdx.y * 64;  // frequency block base (64 freqs per CTA)
    const int b  = blockIdx.z;
    const int token = tokp ? tokp[0] : 1024;

    const int warp_m = warp & 3;     // 4 warps along rows
    const int warp_n = warp >> 2;    // 2 warps along cols
    const int wrow = warp_m * 32;    // warp tile: 32 rows x 64 cols
    const int wcol = warp_n * 64;

    // A-tile generation assignment: thread -> (local freq, 8 consecutive k)
    const int a_n = tid >> 2;            // 0..63
    const int a_k = (tid & 3) * 8;       // {0,8,16,24}
    const int n_freq = nb + a_n;         // 0..511

    // B-tile load assignment: thread -> (k-row, 16 consecutive m)
    const int b_row = tid >> 3;          // 0..31
    const int b_col = (tid & 7) * 16;    // 0..112
    const float* sp = slice + ((size_t)b * KDIM + b_row) * MDIM + m0 + b_col;

    float acc[2][8][4];
    #pragma unroll
    for (int i = 0; i < 2; i++)
        #pragma unroll
        for (int j = 0; j < 8; j++) {
            acc[i][j][0] = 0.f; acc[i][j][1] = 0.f;
            acc[i][j][2] = 0.f; acc[i][j][3] = 0.f;
        }

    const float ang_scale = 6.28318530718f / 8192.0f;

    for (int k0 = 0; k0 < KDIM; k0 += BK) {
        // ---- global load of B tile (issued early; latency overlaps prior mma drain)
        float4 bv[4];
        const float* sp_it = sp + (size_t)k0 * MDIM;
        #pragma unroll
        for (int v = 0; v < 4; v++)
            bv[v] = *(const float4*)(sp_it + v * 4);

        // ---- generate trig A tile values in registers (one sincos -> cos row + sin row)
        float acs[8], asn[8];
        #pragma unroll
        for (int kk = 0; kk < 8; kk++) {
            int kabs = k0 + a_k + kk + token;       // absolute token index
            int p = (kabs * n_freq) & 8191;         // exact integer phase
            if (p >= 4096) p -= 8192;               // center to [-4096, 4095]
            float ang = (float)p * ang_scale;       // in [-pi, pi)
            __sincosf(ang, &asn[kk], &acs[kk]);
        }

        __syncthreads();   // prior iter's smem reads complete

        #pragma unroll
        for (int kk = 0; kk < 8; kk++) {
            As[a_n        * AS_STRIDE + a_k + kk] = f2tf32(acs[kk]);
            As[(a_n + 64) * AS_STRIDE + a_k + kk] = f2tf32(asn[kk]);
        }
        #pragma unroll
        for (int v = 0; v < 4; v++) {
            uint32_t* bp = &Bs[b_row * BS_STRIDE + b_col + v * 4];
            bp[0] = f2tf32(bv[v].x);
            bp[1] = f2tf32(bv[v].y);
            bp[2] = f2tf32(bv[v].z);
            bp[3] = f2tf32(bv[v].w);
        }

        __syncthreads();   // tiles visible

        #pragma unroll
        for (int ks = 0; ks < BK; ks += 8) {
            uint32_t af[2][4];
            #pragma unroll
            for (int i = 0; i < 2; i++) {
                int r = wrow + i * 16;
                af[i][0] = As[(r + g    ) * AS_STRIDE + ks + tig    ];
                af[i][1] = As[(r + g + 8) * AS_STRIDE + ks + tig    ];
                af[i][2] = As[(r + g    ) * AS_STRIDE + ks + tig + 4];
                af[i][3] = As[(r + g + 8) * AS_STRIDE + ks + tig + 4];
            }
            uint32_t bf[8][2];
            #pragma unroll
            for (int j = 0; j < 8; j++) {
                int c = wcol + j * 8 + g;
                bf[j][0] = Bs[(ks + tig    ) * BS_STRIDE + c];
                bf[j][1] = Bs[(ks + tig + 4) * BS_STRIDE + c];
            }
            #pragma unroll
            for (int i = 0; i < 2; i++)
                #pragma unroll
                for (int j = 0; j < 8; j++) {
                    asm volatile(
                        "mma.sync.aligned.m16n8k8.row.col.f32.tf32.tf32.f32 "
                        "{%0,%1,%2,%3}, {%4,%5,%6,%7}, {%8,%9}, {%0,%1,%2,%3};\n"
                        : "+f"(acc[i][j][0]), "+f"(acc[i][j][1]),
                          "+f"(acc[i][j][2]), "+f"(acc[i][j][3])
                        : "r"(af[i][0]), "r"(af[i][1]), "r"(af[i][2]), "r"(af[i][3]),
                          "r"(bf[j][0]), "r"(bf[j][1]));
                }
        }
    }

    // ---- epilogue: out = base + acc
    #pragma unroll
    for (int i = 0; i < 2; i++) {
        int rloc0 = wrow + i * 16 + g;               // local row of c0/c1
        #pragma unroll
        for (int half = 0; half < 2; half++) {
            int rl = rloc0 + half * 8;               // local row 0..127
            int grow = (rl < 64) ? (nb + rl)         // cos rows -> n
                                 : (512 + nb + rl - 64); // sin rows -> 512+n
            size_t rowoff = ((size_t)b * 1024 + grow) * MDIM + m0;
            #pragma unroll
            for (int j = 0; j < 8; j++) {
                int c = wcol + j * 8 + tig * 2;
                float2 bse = *(const float2*)(base + rowoff + c);
                float2 o;
                o.x = bse.x + acc[i][j][half * 2 + 0];
                o.y = bse.y + acc[i][j][half * 2 + 1];
                *(float2*)(out + rowoff + c) = o;
            }
        }
    }
}

extern "C" void kernel_launch(void* const* d_in, const int* in_sizes, int n_in,
                              void* d_out, int out_size)
{
    // Identify inputs by element count (robust to ordering):
    //   base_input : 4*1024*1024 = 4194304 fp32
    //   slice_input: 4*4096*1024 = 16777216 fp32
    //   token_num  : 1 int32
    const float* base  = nullptr;
    const float* slice = nullptr;
    const int*   tok   = nullptr;
    for (int i = 0; i < n_in; i++) {
        if      (in_sizes[i] == 4 * 4096 * 1024) slice = (const float*)d_in[i];
        else if (in_sizes[i] == 4 * 1024 * 1024) base  = (const float*)d_in[i];
        else                                     tok   = (const int*)d_in[i];
    }

    dim3 grid(MDIM / BN, 512 / 64, 4);   // (8, 8, 4) = 256 CTAs
    hippo_tf32_kernel<<<grid, 256>>>(base, slice, tok, (float*)d_out);
}

// round 3
// speedup vs baseline: 2.0153x; 2.0153x over previous
#include <cuda_runtime.h>
#include <cstdint>
#include <cstddef>

// ---------------------------------------------------------------------------
// MultiDimHiPPO2 on sm_100 (non-'a' PTX target: NO tcgen05; legacy mma.sync).
//
//   out[b, f, m] = base[b, f, m] + sum_k T[f,k] * slice[b,k,m]
//   T[f,k] = cos(2pi*(k+tok)*f/8192)        for f in [0,512)
//          = sin(2pi*(k+tok)*(f-512)/8192)  for f in [512,1024)
//
// All operands are pre-shuffled into exact m16n8k8 tf32 fragment order so the
// GEMM mainloop is pure coalesced LDG.128 + HMMA: no smem, no syncthreads.
// ---------------------------------------------------------------------------

#define KDIM    4096
#define MDIM    1024
#define FDIM    1024
#define NSTEP   (KDIM / 8)        // 512 k-steps of 8

// A-fragment store:  Afrag[(rb16*512 + s)*32 + lane] = {a0,a1,a2,a3}
//   a0=T[rb16*16+g][s*8+tig]  a1=T[..+g+8][..tig]  a2=T[..g][..tig+4]  a3=T[..g+8][..tig+4]
__device__ float4 Afrag[64 * NSTEP * 32];                 // 16 MB

// B-fragment store:  Bfrag[(((b*512+s)*16 + nb)*4 + q)*32 + lane]
//   = { B[s8+tig][nb64+2q*8+g],  B[s8+tig+4][same col],
//       B[s8+tig][nb64+(2q+1)*8+g], B[s8+tig+4][same col] }   (B = slice[b])
__device__ float4 Bfrag[4 * NSTEP * 16 * 4 * 32];         // 64 MB

__device__ __forceinline__ uint32_t f2tf32(float x) {
    uint32_t r;
    asm("cvt.rna.tf32.f32 %0, %1;" : "=r"(r) : "f"(x));
    return r;
}
__device__ __forceinline__ float tf32f(float x) {
    return __uint_as_float(f2tf32(x));
}

// exact integer phase -> trig value (tf32-rounded)
__device__ __forceinline__ float trigval(int k, int tok, int n, bool use_sin) {
    int p = ((k + tok) * n) & 8191;
    if (p >= 4096) p -= 8192;
    float ang = (float)p * (6.28318530718f / 8192.0f);
    float v = use_sin ? __sinf(ang) : __cosf(ang);
    return tf32f(v);
}

// ---------------- kernel 1: trig table in A-frag order ----------------
__global__ void __launch_bounds__(256) trig_frag_fill(const int* __restrict__ tokp) {
    int t = blockIdx.x * 256 + threadIdx.x;        // 0 .. 1M-1 (one float4 each)
    int lane = t & 31;
    int s    = (t >> 5) & 511;
    int rb16 = t >> 14;                            // 0..63
    int g   = lane >> 2;
    int tig = lane & 3;
    int token = tokp ? tokp[0] : 1024;

    int f1 = rb16 * 16 + g;                        // row of a0/a2
    int f2 = f1 + 8;                               // row of a1/a3
    bool use_sin = (f1 >= 512);                    // f1,f2 always same half
    int n1 = f1 & 511;
    int n2 = f2 & 511;
    int k1 = s * 8 + tig;
    int k2 = k1 + 4;

    float4 v;
    v.x = trigval(k1, token, n1, use_sin);
    v.y = trigval(k1, token, n2, use_sin);
    v.z = trigval(k2, token, n1, use_sin);
    v.w = trigval(k2, token, n2, use_sin);
    Afrag[t] = v;
}

// ---------------- kernel 2: slice shuffle into B-frag order ----------------
__global__ void __launch_bounds__(256) slice_frag_fill(const float* __restrict__ slice) {
    int t = blockIdx.x * 256 + threadIdx.x;        // 0 .. 1M-1
    int lane = t & 31;
    int nb   = (t >> 5) & 15;
    int s    = (t >> 9) & 511;
    int b    = t >> 18;
    int g   = lane >> 2;
    int tig = lane & 3;

    const float* sp = slice + ((size_t)b * KDIM) * MDIM + nb * 64 + g;
    float v[8][2];
    #pragma unroll
    for (int h = 0; h < 2; h++) {
        int k = s * 8 + tig + 4 * h;
        const float* rp = sp + (size_t)k * MDIM;
        #pragma unroll
        for (int j = 0; j < 8; j++) v[j][h] = rp[j * 8];
    }
    float4* dst = Bfrag + ((size_t)((b * 512 + s) * 16 + nb) * 4) * 32 + lane;
    #pragma unroll
    for (int q = 0; q < 4; q++) {
        float4 o;
        o.x = tf32f(v[2 * q    ][0]);
        o.y = tf32f(v[2 * q    ][1]);
        o.z = tf32f(v[2 * q + 1][0]);
        o.w = tf32f(v[2 * q + 1][1]);
        dst[q * 32] = o;
    }
}

// ---------------- kernel 3: the GEMM ----------------
#define MMA4(acc, av, b0, b1)                                                   \
    asm volatile(                                                               \
        "mma.sync.aligned.m16n8k8.row.col.f32.tf32.tf32.f32 "                   \
        "{%0,%1,%2,%3}, {%4,%5,%6,%7}, {%8,%9}, {%0,%1,%2,%3};\n"               \
        : "+f"((acc)[0]), "+f"((acc)[1]), "+f"((acc)[2]), "+f"((acc)[3])        \
        : "r"(__float_as_uint((av).x)), "r"(__float_as_uint((av).y)),           \
          "r"(__float_as_uint((av).z)), "r"(__float_as_uint((av).w)),           \
          "r"(__float_as_uint(b0)), "r"(__float_as_uint(b1)))

__global__ void __launch_bounds__(256, 1) hippo_gemm(
    const float* __restrict__ base,
    float*       __restrict__ out)
{
    const int tid  = threadIdx.x;
    const int warp = tid >> 5;
    const int lane = tid & 31;
    const int g    = lane >> 2;
    const int tig  = lane & 3;

    const int mb = blockIdx.x;            // 0..3   (256 m per CTA)
    const int fb = blockIdx.y;            // 0..7   (128 freq per CTA)
    const int b  = blockIdx.z;

    const int warp_f = warp & 1;          // 2 freq halves of 64
    const int warp_n = warp >> 1;         // 4 m-chunks of 64
    const int rbg0 = fb * 8 + warp_f * 4; // first 16-row block of this warp
    const int nbg  = mb * 4 + warp_n;     // 64-m block id (0..15)

    const float4* Ap = Afrag + ((size_t)rbg0 * NSTEP) * 32 + lane;   // + s*32 + rb*16384
    const float4* Bp = Bfrag + ((size_t)(b * NSTEP) * 16 + nbg) * 4 * 32 + lane; // + s*2048 + q*32

    float acc[4][8][4];
    #pragma unroll
    for (int rb = 0; rb < 4; rb++)
        #pragma unroll
        for (int j = 0; j < 8; j++)
            #pragma unroll
            for (int c = 0; c < 4; c++) acc[rb][j][c] = 0.f;

    float4 ab[2][4], bb[2][4];
    #pragma unroll
    for (int rb = 0; rb < 4; rb++) ab[0][rb] = Ap[rb * (NSTEP * 32)];
    #pragma unroll
    for (int q = 0; q < 4; q++)    bb[0][q]  = Bp[q * 32];

    #pragma unroll 1
    for (int s = 0; s < NSTEP; s += 2) {
        // prefetch s+1 into buf 1
        {
            const float4* Apn = Ap + (size_t)(s + 1) * 32;
            const float4* Bpn = Bp + (size_t)(s + 1) * 2048;
            #pragma unroll
            for (int rb = 0; rb < 4; rb++) ab[1][rb] = Apn[rb * (NSTEP * 32)];
            #pragma unroll
            for (int q = 0; q < 4; q++)    bb[1][q]  = Bpn[q * 32];
        }
        // mma on buf 0
        #pragma unroll
        for (int rb = 0; rb < 4; rb++)
            #pragma unroll
            for (int j = 0; j < 8; j++) {
                const float4& bq = bb[0][j >> 1];
                if (j & 1) { MMA4(acc[rb][j], ab[0][rb], bq.z, bq.w); }
                else       { MMA4(acc[rb][j], ab[0][rb], bq.x, bq.y); }
            }
        // prefetch s+2 into buf 0
        if (s + 2 < NSTEP) {
            const float4* Apn = Ap + (size_t)(s + 2) * 32;
            const float4* Bpn = Bp + (size_t)(s + 2) * 2048;
            #pragma unroll
            for (int rb = 0; rb < 4; rb++) ab[0][rb] = Apn[rb * (NSTEP * 32)];
            #pragma unroll
            for (int q = 0; q < 4; q++)    bb[0][q]  = Bpn[q * 32];
        }
        // mma on buf 1
        #pragma unroll
        for (int rb = 0; rb < 4; rb++)
            #pragma unroll
            for (int j = 0; j < 8; j++) {
                const float4& bq = bb[1][j >> 1];
                if (j & 1) { MMA4(acc[rb][j], ab[1][rb], bq.z, bq.w); }
                else       { MMA4(acc[rb][j], ab[1][rb], bq.x, bq.y); }
            }
    }

    // ---- epilogue: out = base + acc
    const int col0 = mb * 256 + warp_n * 64 + tig * 2;
    #pragma unroll
    for (int rb = 0; rb < 4; rb++) {
        int r0 = (rbg0 + rb) * 16 + g;
        size_t off0 = ((size_t)(b * FDIM + r0)) * MDIM + col0;
        size_t off1 = off0 + (size_t)8 * MDIM;
        #pragma unroll
        for (int j = 0; j < 8; j++) {
            size_t o0 = off0 + j * 8;
            size_t o1 = off1 + j * 8;
            float2 b0 = *(const float2*)(base + o0);
            float2 b1 = *(const float2*)(base + o1);
            float2 w0, w1;
            w0.x = b0.x + acc[rb][j][0];
            w0.y = b0.y + acc[rb][j][1];
            w1.x = b1.x + acc[rb][j][2];
            w1.y = b1.y + acc[rb][j][3];
            *(float2*)(out + o0) = w0;
            *(float2*)(out + o1) = w1;
        }
    }
}

// ---------------- host launch ----------------
extern "C" void kernel_launch(void* const* d_in, const int* in_sizes, int n_in,
                              void* d_out, int out_size)
{
    const float* base  = nullptr;
    const float* slice = nullptr;
    const int*   tok   = nullptr;
    for (int i = 0; i < n_in; i++) {
        if      (in_sizes[i] == 4 * 4096 * 1024) slice = (const float*)d_in[i];
        else if (in_sizes[i] == 4 * 1024 * 1024) base  = (const float*)d_in[i];
        else                                     tok   = (const int*)d_in[i];
    }
    if (!base  && n_in > 0) base  = (const float*)d_in[0];
    if (!slice && n_in > 1) slice = (const float*)d_in[1];

    trig_frag_fill <<<4096, 256>>>(tok);
    slice_frag_fill<<<4096, 256>>>(slice);

    dim3 grid(4, 8, 4);   // m-blocks(256) x f-blocks(128) x batch = 128 CTAs
    hippo_gemm<<<grid, 256>>>(base, (float*)d_out);
}